// round 14
// baseline (speedup 1.0000x reference)
#include <cuda_runtime.h>
#include <cuda_bf16.h>
#include <cstdint>

#define DD 64
#define HH 256
#define ROWS 64            // rows per CTA
#define THREADS 512        // 16 warps = 4 row-stripes x 4 jj-parts

// padded bf16 strides (elements)
#define YSTR  136
#define W1STR 136
#define W2STR 520

#define W1IMG_BYTES (HH * W1STR * 2)   // 69632
#define W2IMG_BYTES (DD * W2STR * 2)   // 66560

#define SM_Y   0
#define SM_W1  (SM_Y  + ROWS * YSTR * 2)          // 17408
#define SM_W2  (SM_W1 + W1IMG_BYTES)              // 87040
#define SM_Z   (SM_W2 + W2IMG_BYTES)              // 153600
#define SM_S   (SM_Z + HH * 4)
#define SM_B2  (SM_S + HH * 4)
#define SMEM_TOTAL (SM_B2 + DD * 4 + 16)

// post-mainloop reuse of [SM_Y .. SM_W2): partials + div partials
#define PSTR   68
#define SM_P   0                            // float [4][64][PSTR] = 69632 B
#define SM_DV  (4 * ROWS * PSTR * 4)        // float [4][64] = 1024 B

__device__ __align__(16) unsigned char g_w1img[W1IMG_BYTES];
__device__ __align__(16) unsigned char g_w2img[W2IMG_BYTES];
__device__ __align__(16) float g_z[HH];
__device__ __align__(16) float g_s[HH];
__device__ __align__(16) float g_b2[DD];

__device__ __forceinline__ uint32_t smem_u32(const void* p) {
    uint32_t a;
    asm("{ .reg .u64 t; cvta.to.shared.u64 t, %1; cvt.u32.u64 %0, t; }" : "=r"(a) : "l"(p));
    return a;
}
__device__ __forceinline__ float tanh_ap(float x) {
    float r; asm("tanh.approx.f32 %0, %1;" : "=f"(r) : "f"(x)); return r;
}
__device__ __forceinline__ uint32_t packbf(float lo, float hi) {
    uint32_t r;
    asm("cvt.rn.bf16x2.f32 %0, %1, %2;" : "=r"(r) : "f"(hi), "f"(lo));
    return r;   // low 16 = lo operand
}
__device__ __forceinline__ void mma_bf16(float c[4], const uint32_t a[4], const uint32_t b[2]) {
    asm volatile("mma.sync.aligned.m16n8k16.row.col.f32.bf16.bf16.f32 "
        "{%0,%1,%2,%3}, {%4,%5,%6,%7}, {%8,%9}, {%0,%1,%2,%3};"
        : "+f"(c[0]), "+f"(c[1]), "+f"(c[2]), "+f"(c[3])
        : "r"(a[0]), "r"(a[1]), "r"(a[2]), "r"(a[3]), "r"(b[0]), "r"(b[1]));
}
#define LDM4(R, addr) asm volatile( \
    "ldmatrix.sync.aligned.m8n8.x4.shared.b16 {%0,%1,%2,%3}, [%4];" \
    : "=r"((R)[0]), "=r"((R)[1]), "=r"((R)[2]), "=r"((R)[3]) : "r"(addr))

// ============ prep kernel: convert weights once (fully parallel) ============
__global__ __launch_bounds__(256, 1)
void ode_prep(const float* __restrict__ tptr, const float* __restrict__ W1,
              const float* __restrict__ b1, const float* __restrict__ wt,
              const float* __restrict__ W2, const float* __restrict__ b2)
{
    // allow the dependent (main) kernel to launch & run its Y prologue now
    asm volatile("griddepcontrol.launch_dependents;" ::: "memory");

    const int gidx = blockIdx.x * 256 + threadIdx.x;   // 0..16383 (grid 64)
    __nv_bfloat16* w1i = (__nv_bfloat16*)g_w1img;
    __nv_bfloat16* w2i = (__nv_bfloat16*)g_w2img;
    {   // W1 [d][j] -> image[j][d | 64+d]
        int d = gidx >> 8, j = gidx & 255;
        float v = W1[gidx];
        __nv_bfloat16 h = __float2bfloat16(v);
        w1i[j * W1STR + d]      = h;
        w1i[j * W1STR + 64 + d] = __float2bfloat16(v - __bfloat162float(h));
    }
    {   // W2 [hr][n] -> image[n][hr | 256+hr]
        int hr = gidx >> 6, n = gidx & 63;
        float v = W2[gidx];
        __nv_bfloat16 h = __float2bfloat16(v);
        w2i[n * W2STR + hr]       = h;
        w2i[n * W2STR + 256 + hr] = __float2bfloat16(v - __bfloat162float(h));
    }
    // s_j: warp-per-j reduction
    if (gidx < 8192) {
        const int j = gidx >> 5, d = gidx & 31;
        float p = W1[d * HH + j] * W2[j * DD + d]
                + W1[(d + 32) * HH + j] * W2[j * DD + d + 32];
        p += __shfl_xor_sync(0xffffffffu, p, 1);
        p += __shfl_xor_sync(0xffffffffu, p, 2);
        p += __shfl_xor_sync(0xffffffffu, p, 4);
        p += __shfl_xor_sync(0xffffffffu, p, 8);
        p += __shfl_xor_sync(0xffffffffu, p, 16);
        if (d == 0) g_s[j] = p;
    }
    if (gidx < HH) g_z[gidx] = tptr[0] * wt[gidx] + b1[gidx];
    if (gidx < DD) g_b2[gidx] = b2[gidx];
}

// ============ main kernel ============
__global__ __launch_bounds__(THREADS, 1)
void ode_mma(const float* __restrict__ y, float* __restrict__ out)
{
    extern __shared__ char smc[];
    float* sz  = (float*)(smc + SM_Z);
    float* ss  = (float*)(smc + SM_S);
    float* sbb = (float*)(smc + SM_B2);

    const uint32_t sbase = smem_u32(smc);
    const int tid  = threadIdx.x;
    const int lane = tid & 31;
    const int warp = tid >> 5;
    const int stripe = warp & 3;          // 16-row stripe
    const int part   = warp >> 2;         // jj quarter (0..3)

    // ---- phase A (overlaps prep): Y conversion, weight-independent ----
    {
        const float2* yb = (const float2*)(y + (size_t)blockIdx.x * ROWS * DD);
        uint32_t* sy32 = (uint32_t*)(smc + SM_Y);
        #pragma unroll
        for (int i = tid; i < ROWS * DD / 2; i += THREADS) {
            const int r = i >> 5, dp = (i & 31);
            float2 v = yb[i];
            uint32_t u0 = __float_as_uint(v.x), u1 = __float_as_uint(v.y);
            uint32_t hi = __byte_perm(u0, u1, 0x7632);
            float l0 = v.x - __uint_as_float(u0 & 0xFFFF0000u);
            float l1 = v.y - __uint_as_float(u1 & 0xFFFF0000u);
            sy32[r * (YSTR / 2) + dp]      = hi;
            sy32[r * (YSTR / 2) + 32 + dp] = packbf(l0, l1);
        }
    }

    // ---- wait for prep's global writes, then pull images ----
    asm volatile("griddepcontrol.wait;" ::: "memory");
    {
        const float4* s1 = (const float4*)g_w1img;
        float4* d1 = (float4*)(smc + SM_W1);
        #pragma unroll
        for (int i = tid; i < W1IMG_BYTES / 16; i += THREADS) d1[i] = s1[i];
        const float4* s2 = (const float4*)g_w2img;
        float4* d2 = (float4*)(smc + SM_W2);
        #pragma unroll
        for (int i = tid; i < W2IMG_BYTES / 16; i += THREADS) d2[i] = s2[i];
        if (tid < HH) { sz[tid] = g_z[tid]; ss[tid] = g_s[tid]; }
        if (tid < DD) sbb[tid] = g_b2[tid];
    }
    __syncthreads();

    // ---- per-warp: 16-row stripe, quarter of hidden dim ----
    const int r0 = stripe * 16;

    uint32_t yhi[4][4], ylo[4][4];
    {
        const int arow = r0 + (lane & 7) + ((lane >> 3) & 1) * 8;
        const int acol = ((lane >> 4) & 1) * 8;
        const uint32_t abase = sbase + SM_Y + (uint32_t)arow * (YSTR * 2);
        #pragma unroll
        for (int kk = 0; kk < 4; kk++) {
            LDM4(yhi[kk], abase + (uint32_t)(kk * 16 + acol) * 2);
            LDM4(ylo[kk], abase + (uint32_t)(64 + kk * 16 + acol) * 2);
        }
    }

    float acc2[8][4];
    #pragma unroll
    for (int t = 0; t < 8; t++)
        #pragma unroll
        for (int i = 0; i < 4; i++) acc2[t][i] = 0.f;
    float dvlo = 0.f, dvhi = 0.f;

    const int qq = (lane & 3) * 2;
    const uint32_t w1lo_off = (uint32_t)(lane & 7) * (W1STR * 2)
        + (uint32_t)(((lane >> 3) & 1) * 8 + ((lane >> 4) & 1) * 64) * 2;
    const uint32_t w2lo_off = (uint32_t)(lane & 7) * (W2STR * 2)
        + (uint32_t)(((lane >> 3) & 1) * 8 + ((lane >> 4) & 1) * 256) * 2;

    const int jjBeg = part * 4;
    #pragma unroll
    for (int u = 0; u < 4; u++) {
        const int jj = jjBeg + u;

        // ---- GEMM1: 3 independent chains per n8 fragment ----
        float cfA[2][4], cfB[2][4], cfC[2][4];
        #pragma unroll
        for (int p = 0; p < 2; p++) {
            const int j0p = jj * 16 + p * 8;
            float2 zz = *(const float2*)(sz + j0p + qq);
            cfA[p][0] = zz.x; cfA[p][1] = zz.y; cfA[p][2] = zz.x; cfA[p][3] = zz.y;
            #pragma unroll
            for (int i = 0; i < 4; i++) { cfB[p][i] = 0.f; cfC[p][i] = 0.f; }

            const uint32_t bbase = sbase + SM_W1 + (uint32_t)j0p * (W1STR * 2) + w1lo_off;
            #pragma unroll
            for (int kk = 0; kk < 4; kk++) {
                uint32_t bf[4];                      // [0:2)=hi, [2:4)=lo
                LDM4(bf, bbase + (uint32_t)kk * 32);
                mma_bf16(cfA[p], yhi[kk], bf);
                mma_bf16(cfB[p], ylo[kk], bf);
                mma_bf16(cfC[p], yhi[kk], bf + 2);
            }
        }

        // ---- epilogue-1: tanh + cheap truncation split ----
        uint32_t Ah[4], Al[4];
        float hv[2][4];
        #pragma unroll
        for (int p = 0; p < 2; p++) {
            float h0 = tanh_ap((cfA[p][0] + cfB[p][0]) + cfC[p][0]);
            float h1 = tanh_ap((cfA[p][1] + cfB[p][1]) + cfC[p][1]);
            float h2 = tanh_ap((cfA[p][2] + cfB[p][2]) + cfC[p][2]);
            float h3 = tanh_ap((cfA[p][3] + cfB[p][3]) + cfC[p][3]);
            hv[p][0] = h0; hv[p][1] = h1; hv[p][2] = h2; hv[p][3] = h3;
            uint32_t u0 = __float_as_uint(h0), u1 = __float_as_uint(h1);
            uint32_t u2 = __float_as_uint(h2), u3 = __float_as_uint(h3);
            Ah[p * 2 + 0] = __byte_perm(u0, u1, 0x7632);
            Ah[p * 2 + 1] = __byte_perm(u2, u3, 0x7632);
            Al[p * 2 + 0] = packbf(h0 - __uint_as_float(u0 & 0xFFFF0000u),
                                   h1 - __uint_as_float(u1 & 0xFFFF0000u));
            Al[p * 2 + 1] = packbf(h2 - __uint_as_float(u2 & 0xFFFF0000u),
                                   h3 - __uint_as_float(u3 & 0xFFFF0000u));
        }

        // ---- GEMM2: 8 independent chains ----
        const uint32_t b2base = sbase + SM_W2 + (uint32_t)(jj * 16) * 2 + w2lo_off;
        #pragma unroll
        for (int t = 0; t < 8; t++) {
            uint32_t bf[4];
            LDM4(bf, b2base + (uint32_t)t * 8 * (W2STR * 2));
            mma_bf16(acc2[t], Ah, bf);
            mma_bf16(acc2[t], Al, bf);
            mma_bf16(acc2[t], Ah, bf + 2);
        }

        // ---- divergence FMAs ----
        #pragma unroll
        for (int p = 0; p < 2; p++) {
            float2 sv = *(const float2*)(ss + jj * 16 + p * 8 + qq);
            dvlo += (1.f - hv[p][0] * hv[p][0]) * sv.x + (1.f - hv[p][1] * hv[p][1]) * sv.y;
            dvhi += (1.f - hv[p][2] * hv[p][2]) * sv.x + (1.f - hv[p][3] * hv[p][3]) * sv.y;
        }
    }

    // ---- combine the 4 jj-quarters via smem ----
    __syncthreads();
    {
        float* sP  = (float*)(smc + SM_P);   // [4][64][PSTR]
        float* sDv = (float*)(smc + SM_DV);  // [4][64]
        const int rA = r0 + (lane >> 2);
        const int rB = rA + 8;
        float* pA = sP + ((size_t)part * ROWS + rA) * PSTR + qq;
        float* pB = sP + ((size_t)part * ROWS + rB) * PSTR + qq;
        #pragma unroll
        for (int t = 0; t < 8; t++) {
            *(float2*)(pA + t * 8) = make_float2(acc2[t][0], acc2[t][1]);
            *(float2*)(pB + t * 8) = make_float2(acc2[t][2], acc2[t][3]);
        }
        dvlo += __shfl_xor_sync(0xffffffffu, dvlo, 1);
        dvlo += __shfl_xor_sync(0xffffffffu, dvlo, 2);
        dvhi += __shfl_xor_sync(0xffffffffu, dvhi, 1);
        dvhi += __shfl_xor_sync(0xffffffffu, dvhi, 2);
        if ((lane & 3) == 0) {
            sDv[part * ROWS + rA] = dvlo;
            sDv[part * ROWS + rB] = dvhi;
        }
    }
    __syncthreads();

    // ---- final: sum 4 partials + b2 -> out ----
    {
        const float* sP  = (const float*)(smc + SM_P);
        const float* sDv = (const float*)(smc + SM_DV);
        const int r  = tid >> 3;             // 0..63
        const int c0 = (tid & 7) * 8;
        float* op = out + (size_t)(blockIdx.x * ROWS + r) * (DD + 1);
        #pragma unroll
        for (int i = 0; i < 2; i++) {
            const int c = c0 + i * 4;
            float4 a0 = *(const float4*)(sP + (size_t)(0 * ROWS + r) * PSTR + c);
            float4 a1 = *(const float4*)(sP + (size_t)(1 * ROWS + r) * PSTR + c);
            float4 a2 = *(const float4*)(sP + (size_t)(2 * ROWS + r) * PSTR + c);
            float4 a3 = *(const float4*)(sP + (size_t)(3 * ROWS + r) * PSTR + c);
            float4 bb = *(const float4*)(sbb + c);
            op[c + 0] = ((a0.x + a1.x) + (a2.x + a3.x)) + bb.x;
            op[c + 1] = ((a0.y + a1.y) + (a2.y + a3.y)) + bb.y;
            op[c + 2] = ((a0.z + a1.z) + (a2.z + a3.z)) + bb.z;
            op[c + 3] = ((a0.w + a1.w) + (a2.w + a3.w)) + bb.w;
        }
        if ((tid & 7) == 0)
            op[DD] = -((sDv[r] + sDv[ROWS + r]) + (sDv[2 * ROWS + r] + sDv[3 * ROWS + r]));
    }
}

extern "C" void kernel_launch(void* const* d_in, const int* in_sizes, int n_in,
                              void* d_out, int out_size) {
    const float* t  = (const float*)d_in[0];
    const float* y  = (const float*)d_in[1];
    const float* W1 = (const float*)d_in[2];
    const float* b1 = (const float*)d_in[3];
    const float* wt = (const float*)d_in[4];
    const float* W2 = (const float*)d_in[5];
    const float* b2 = (const float*)d_in[6];
    float* out = (float*)d_out;

    const int n = in_sizes[1] / DD;          // 8192
    const int blocks = n / ROWS;             // 128

    ode_prep<<<64, 256>>>(t, W1, b1, wt, W2, b2);

    cudaFuncSetAttribute(ode_mma,
                         cudaFuncAttributeMaxDynamicSharedMemorySize, SMEM_TOTAL);

    // PDL: launch main so it overlaps prep; griddepcontrol.wait inside
    // guarantees prep's global writes are visible before image copy.
    cudaLaunchConfig_t cfg = {};
    cfg.gridDim  = dim3(blocks, 1, 1);
    cfg.blockDim = dim3(THREADS, 1, 1);
    cfg.dynamicSmemBytes = SMEM_TOTAL;
    cudaLaunchAttribute attr[1];
    attr[0].id = cudaLaunchAttributeProgrammaticStreamSerialization;
    attr[0].val.programmaticStreamSerializationAllowed = 1;
    cfg.attrs = attr;
    cfg.numAttrs = 1;
    cudaLaunchKernelEx(&cfg, ode_mma, (const float*)y, (float*)out);
}

// round 15
// speedup vs baseline: 1.0835x; 1.0835x over previous
#include <cuda_runtime.h>
#include <cuda_bf16.h>
#include <cstdint>

#define DD 64
#define HH 256
#define ROWS 64            // rows per CTA
#define THREADS 512        // 16 warps = 4 row-stripes x 4 jj-parts

// padded bf16 strides (elements)
#define YSTR  136
#define W1STR 136
#define W2STR 520

#define W1IMG_BYTES (HH * W1STR * 2)   // 69632
#define W2IMG_BYTES (DD * W2STR * 2)   // 66560

#define SM_Y   0
#define SM_W1  (SM_Y  + ROWS * YSTR * 2)          // 17408
#define SM_W2  (SM_W1 + W1IMG_BYTES)              // 87040
#define SM_Z   (SM_W2 + W2IMG_BYTES)              // 153600
#define SM_S   (SM_Z + HH * 4)
#define SM_B2  (SM_S + HH * 4)
#define SMEM_TOTAL (SM_B2 + DD * 4 + 16)

// raw fp32 staging (in-place with images; odd word strides -> conflict-light)
#define RSTR1 257          // W1 raw: 64 rows x 257 words = 65792 B <= W1IMG_BYTES
#define RSTR2 65           // W2 raw: 256 rows x 65 words = 66560 B == W2IMG_BYTES

// post-mainloop reuse of [SM_Y .. SM_W2): partials + div partials
#define PSTR   68
#define SM_P   0                            // float [4][64][PSTR] = 69632 B
#define SM_DV  (4 * ROWS * PSTR * 4)        // float [4][64] = 1024 B

__device__ __forceinline__ uint32_t smem_u32(const void* p) {
    uint32_t a;
    asm("{ .reg .u64 t; cvta.to.shared.u64 t, %1; cvt.u32.u64 %0, t; }" : "=r"(a) : "l"(p));
    return a;
}
__device__ __forceinline__ float tanh_ap(float x) {
    float r; asm("tanh.approx.f32 %0, %1;" : "=f"(r) : "f"(x)); return r;
}
__device__ __forceinline__ uint32_t packbf(float lo, float hi) {
    uint32_t r;
    asm("cvt.rn.bf16x2.f32 %0, %1, %2;" : "=r"(r) : "f"(hi), "f"(lo));
    return r;   // low 16 = lo operand
}
__device__ __forceinline__ float truncbf(uint32_t u) {
    return __uint_as_float(u & 0xFFFF0000u);
}
__device__ __forceinline__ void mma_bf16(float c[4], const uint32_t a[4], const uint32_t b[2]) {
    asm volatile("mma.sync.aligned.m16n8k16.row.col.f32.bf16.bf16.f32 "
        "{%0,%1,%2,%3}, {%4,%5,%6,%7}, {%8,%9}, {%0,%1,%2,%3};"
        : "+f"(c[0]), "+f"(c[1]), "+f"(c[2]), "+f"(c[3])
        : "r"(a[0]), "r"(a[1]), "r"(a[2]), "r"(a[3]), "r"(b[0]), "r"(b[1]));
}
#define LDM4(R, addr) asm volatile( \
    "ldmatrix.sync.aligned.m8n8.x4.shared.b16 {%0,%1,%2,%3}, [%4];" \
    : "=r"((R)[0]), "=r"((R)[1]), "=r"((R)[2]), "=r"((R)[3]) : "r"(addr))

__global__ __launch_bounds__(THREADS, 1)
void ode_mma(const float* __restrict__ tptr, const float* __restrict__ y,
             const float* __restrict__ W1, const float* __restrict__ b1,
             const float* __restrict__ wt, const float* __restrict__ W2,
             const float* __restrict__ b2, float* __restrict__ out)
{
    extern __shared__ char smc[];
    float* sz  = (float*)(smc + SM_Z);
    float* ss  = (float*)(smc + SM_S);
    float* sbb = (float*)(smc + SM_B2);
    float* raw1 = (float*)(smc + SM_W1);
    float* raw2 = (float*)(smc + SM_W2);

    const uint32_t sbase = smem_u32(smc);
    const int tid  = threadIdx.x;
    const int lane = tid & 31;
    const int warp = tid >> 5;
    const int stripe = warp & 3;          // 16-row stripe
    const int part   = warp >> 2;         // jj quarter (0..3)

    // ======== phase A: coalesced raw staging + Y convert + consts ========
    #pragma unroll
    for (int k = 0; k < 32; k++) {        // W1 raw: [d][j] -> raw1[d*257 + j]
        const int g = tid + k * THREADS;
        raw1[(g >> 8) * RSTR1 + (g & 255)] = W1[g];
    }
    #pragma unroll
    for (int k = 0; k < 32; k++) {        // W2 raw: [hr][n] -> raw2[hr*65 + n]
        const int g = tid + k * THREADS;
        raw2[(g >> 6) * RSTR2 + (g & 63)] = W2[g];
    }
    {
        const float2* yb = (const float2*)(y + (size_t)blockIdx.x * ROWS * DD);
        uint32_t* sy32 = (uint32_t*)(smc + SM_Y);
        #pragma unroll
        for (int i = tid; i < ROWS * DD / 2; i += THREADS) {
            const int r = i >> 5, dp = (i & 31);
            float2 v = yb[i];
            uint32_t u0 = __float_as_uint(v.x), u1 = __float_as_uint(v.y);
            sy32[r * (YSTR / 2) + dp]      = __byte_perm(u0, u1, 0x7632);
            sy32[r * (YSTR / 2) + 32 + dp] = packbf(v.x - truncbf(u0), v.y - truncbf(u1));
        }
    }
    if (tid < HH) sz[tid] = tptr[0] * wt[tid] + b1[tid];
    if (tid < DD) sbb[tid] = b2[tid];
    __syncthreads();   // sync0: raws staged

    // ---- s_j = sum_d W1[d,j]*W2[j,d] from raws (2 threads per j) ----
    {
        const int j = tid >> 1, half = tid & 1;
        float p = 0.f;
        #pragma unroll
        for (int d0 = 0; d0 < 32; d0++) {
            const int d = half * 32 + d0;
            p += raw1[d * RSTR1 + j] * raw2[j * RSTR2 + d];
        }
        p += __shfl_xor_sync(0xffffffffu, p, 1);
        if (half == 0) ss[j] = p;
    }
    // ---- read W1 raw columns into regs (2-way LDS conflicts) ----
    float ra[16], rc[16];
    #pragma unroll
    for (int k = 0; k < 16; k++) {
        const int idx = tid + k * THREADS;        // hi-word id: j = idx>>5, dp = idx&31
        const int j = idx >> 5, dp = idx & 31;
        ra[k] = raw1[(2 * dp) * RSTR1 + j];
        rc[k] = raw1[(2 * dp + 1) * RSTR1 + j];
    }
    __syncthreads();   // sync1: raw1 fully read
    // ---- write W1 image (conflict-free: lanes walk consecutive words) ----
    {
        uint32_t* w1w = (uint32_t*)(smc + SM_W1);
        #pragma unroll
        for (int k = 0; k < 16; k++) {
            const int idx = tid + k * THREADS;
            const int j = idx >> 5, dp = idx & 31;
            uint32_t ua = __float_as_uint(ra[k]), uc = __float_as_uint(rc[k]);
            w1w[j * (W1STR / 2) + dp]      = __byte_perm(ua, uc, 0x7632);
            w1w[j * (W1STR / 2) + 32 + dp] = packbf(ra[k] - truncbf(ua), rc[k] - truncbf(uc));
        }
    }
    // ---- read W2 raw columns into regs ----
    #pragma unroll
    for (int k = 0; k < 16; k++) {
        const int idx = tid + k * THREADS;        // hi-word id: n = idx>>7, hp = idx&127
        const int n = idx >> 7, hp = idx & 127;
        ra[k] = raw2[(2 * hp) * RSTR2 + n];
        rc[k] = raw2[(2 * hp + 1) * RSTR2 + n];
    }
    __syncthreads();   // sync2: raw2 fully read
    // ---- write W2 image ----
    {
        uint32_t* w2w = (uint32_t*)(smc + SM_W2);
        #pragma unroll
        for (int k = 0; k < 16; k++) {
            const int idx = tid + k * THREADS;
            const int n = idx >> 7, hp = idx & 127;
            uint32_t ua = __float_as_uint(ra[k]), uc = __float_as_uint(rc[k]);
            w2w[n * (W2STR / 2) + hp]       = __byte_perm(ua, uc, 0x7632);
            w2w[n * (W2STR / 2) + 128 + hp] = packbf(ra[k] - truncbf(ua), rc[k] - truncbf(uc));
        }
    }
    __syncthreads();   // sync3: images ready

    // ======== per-warp: 16-row stripe, quarter of hidden dim ========
    const int r0 = stripe * 16;

    uint32_t yhi[4][4], ylo[4][4];
    {
        const int arow = r0 + (lane & 7) + ((lane >> 3) & 1) * 8;
        const int acol = ((lane >> 4) & 1) * 8;
        const uint32_t abase = sbase + SM_Y + (uint32_t)arow * (YSTR * 2);
        #pragma unroll
        for (int kk = 0; kk < 4; kk++) {
            LDM4(yhi[kk], abase + (uint32_t)(kk * 16 + acol) * 2);
            LDM4(ylo[kk], abase + (uint32_t)(64 + kk * 16 + acol) * 2);
        }
    }

    float acc2[8][4];
    #pragma unroll
    for (int t = 0; t < 8; t++)
        #pragma unroll
        for (int i = 0; i < 4; i++) acc2[t][i] = 0.f;
    float dvlo = 0.f, dvhi = 0.f;

    const int qq = (lane & 3) * 2;
    const uint32_t w1lo_off = (uint32_t)(lane & 7) * (W1STR * 2)
        + (uint32_t)(((lane >> 3) & 1) * 8 + ((lane >> 4) & 1) * 64) * 2;
    const uint32_t w2lo_off = (uint32_t)(lane & 7) * (W2STR * 2)
        + (uint32_t)(((lane >> 3) & 1) * 8 + ((lane >> 4) & 1) * 256) * 2;

    const int jjBeg = part * 4;
    #pragma unroll
    for (int u = 0; u < 4; u++) {
        const int jj = jjBeg + u;

        // ---- GEMM1: 3 independent chains per n8 fragment ----
        float cfA[2][4], cfB[2][4], cfC[2][4];
        #pragma unroll
        for (int p = 0; p < 2; p++) {
            const int j0p = jj * 16 + p * 8;
            float2 zz = *(const float2*)(sz + j0p + qq);
            cfA[p][0] = zz.x; cfA[p][1] = zz.y; cfA[p][2] = zz.x; cfA[p][3] = zz.y;
            #pragma unroll
            for (int i = 0; i < 4; i++) { cfB[p][i] = 0.f; cfC[p][i] = 0.f; }

            const uint32_t bbase = sbase + SM_W1 + (uint32_t)j0p * (W1STR * 2) + w1lo_off;
            #pragma unroll
            for (int kk = 0; kk < 4; kk++) {
                uint32_t bf[4];                      // [0:2)=hi, [2:4)=lo
                LDM4(bf, bbase + (uint32_t)kk * 32);
                mma_bf16(cfA[p], yhi[kk], bf);
                mma_bf16(cfB[p], ylo[kk], bf);
                mma_bf16(cfC[p], yhi[kk], bf + 2);
            }
        }

        // ---- epilogue-1: tanh + cheap truncation split ----
        uint32_t Ah[4], Al[4];
        float hv[2][4];
        #pragma unroll
        for (int p = 0; p < 2; p++) {
            float h0 = tanh_ap((cfA[p][0] + cfB[p][0]) + cfC[p][0]);
            float h1 = tanh_ap((cfA[p][1] + cfB[p][1]) + cfC[p][1]);
            float h2 = tanh_ap((cfA[p][2] + cfB[p][2]) + cfC[p][2]);
            float h3 = tanh_ap((cfA[p][3] + cfB[p][3]) + cfC[p][3]);
            hv[p][0] = h0; hv[p][1] = h1; hv[p][2] = h2; hv[p][3] = h3;
            uint32_t u0 = __float_as_uint(h0), u1 = __float_as_uint(h1);
            uint32_t u2 = __float_as_uint(h2), u3 = __float_as_uint(h3);
            Ah[p * 2 + 0] = __byte_perm(u0, u1, 0x7632);
            Ah[p * 2 + 1] = __byte_perm(u2, u3, 0x7632);
            Al[p * 2 + 0] = packbf(h0 - truncbf(u0), h1 - truncbf(u1));
            Al[p * 2 + 1] = packbf(h2 - truncbf(u2), h3 - truncbf(u3));
        }

        // ---- GEMM2: 8 independent chains ----
        const uint32_t b2base = sbase + SM_W2 + (uint32_t)(jj * 16) * 2 + w2lo_off;
        #pragma unroll
        for (int t = 0; t < 8; t++) {
            uint32_t bf[4];
            LDM4(bf, b2base + (uint32_t)t * 8 * (W2STR * 2));
            mma_bf16(acc2[t], Ah, bf);
            mma_bf16(acc2[t], Al, bf);
            mma_bf16(acc2[t], Ah, bf + 2);
        }

        // ---- divergence FMAs ----
        #pragma unroll
        for (int p = 0; p < 2; p++) {
            float2 sv = *(const float2*)(ss + jj * 16 + p * 8 + qq);
            dvlo += (1.f - hv[p][0] * hv[p][0]) * sv.x + (1.f - hv[p][1] * hv[p][1]) * sv.y;
            dvhi += (1.f - hv[p][2] * hv[p][2]) * sv.x + (1.f - hv[p][3] * hv[p][3]) * sv.y;
        }
    }

    // ---- combine the 4 jj-quarters via smem ----
    __syncthreads();
    {
        float* sP  = (float*)(smc + SM_P);   // [4][64][PSTR]
        float* sDv = (float*)(smc + SM_DV);  // [4][64]
        const int rA = r0 + (lane >> 2);
        const int rB = rA + 8;
        float* pA = sP + ((size_t)part * ROWS + rA) * PSTR + qq;
        float* pB = sP + ((size_t)part * ROWS + rB) * PSTR + qq;
        #pragma unroll
        for (int t = 0; t < 8; t++) {
            *(float2*)(pA + t * 8) = make_float2(acc2[t][0], acc2[t][1]);
            *(float2*)(pB + t * 8) = make_float2(acc2[t][2], acc2[t][3]);
        }
        dvlo += __shfl_xor_sync(0xffffffffu, dvlo, 1);
        dvlo += __shfl_xor_sync(0xffffffffu, dvlo, 2);
        dvhi += __shfl_xor_sync(0xffffffffu, dvhi, 1);
        dvhi += __shfl_xor_sync(0xffffffffu, dvhi, 2);
        if ((lane & 3) == 0) {
            sDv[part * ROWS + rA] = dvlo;
            sDv[part * ROWS + rB] = dvhi;
        }
    }
    __syncthreads();

    // ---- final: sum 4 partials + b2 -> out ----
    {
        const float* sP  = (const float*)(smc + SM_P);
        const float* sDv = (const float*)(smc + SM_DV);
        const int r  = tid >> 3;             // 0..63
        const int c0 = (tid & 7) * 8;
        float* op = out + (size_t)(blockIdx.x * ROWS + r) * (DD + 1);
        #pragma unroll
        for (int i = 0; i < 2; i++) {
            const int c = c0 + i * 4;
            float4 a0 = *(const float4*)(sP + (size_t)(0 * ROWS + r) * PSTR + c);
            float4 a1 = *(const float4*)(sP + (size_t)(1 * ROWS + r) * PSTR + c);
            float4 a2 = *(const float4*)(sP + (size_t)(2 * ROWS + r) * PSTR + c);
            float4 a3 = *(const float4*)(sP + (size_t)(3 * ROWS + r) * PSTR + c);
            float4 bb = *(const float4*)(sbb + c);
            op[c + 0] = ((a0.x + a1.x) + (a2.x + a3.x)) + bb.x;
            op[c + 1] = ((a0.y + a1.y) + (a2.y + a3.y)) + bb.y;
            op[c + 2] = ((a0.z + a1.z) + (a2.z + a3.z)) + bb.z;
            op[c + 3] = ((a0.w + a1.w) + (a2.w + a3.w)) + bb.w;
        }
        if ((tid & 7) == 0)
            op[DD] = -((sDv[r] + sDv[ROWS + r]) + (sDv[2 * ROWS + r] + sDv[3 * ROWS + r]));
    }
}

extern "C" void kernel_launch(void* const* d_in, const int* in_sizes, int n_in,
                              void* d_out, int out_size) {
    const float* t  = (const float*)d_in[0];
    const float* y  = (const float*)d_in[1];
    const float* W1 = (const float*)d_in[2];
    const float* b1 = (const float*)d_in[3];
    const float* wt = (const float*)d_in[4];
    const float* W2 = (const float*)d_in[5];
    const float* b2 = (const float*)d_in[6];
    float* out = (float*)d_out;

    const int n = in_sizes[1] / DD;          // 8192
    const int blocks = n / ROWS;             // 128

    cudaFuncSetAttribute(ode_mma,
                         cudaFuncAttributeMaxDynamicSharedMemorySize, SMEM_TOTAL);
    ode_mma<<<blocks, THREADS, SMEM_TOTAL>>>(t, y, W1, b1, wt, W2, b2, out);
}